// round 4
// baseline (speedup 1.0000x reference)
#include <cuda_runtime.h>
#include <cuda_bf16.h>
#include <cstdint>

#define Bq 8
#define Nq 1024
#define Cq 768
#define Hq 12
#define HDq 64
#define Rq 16
#define ROWS (Bq*Nq)          // 8192
#define SCALE 0.125f

typedef unsigned long long ull;
typedef __nv_bfloat16 bf16;

// ---------------- f32x2 helpers ----------------
__device__ __forceinline__ ull pk2(float x, float y) {
    ull r;
    asm("mov.b64 %0, {%1, %2};" : "=l"(r) : "r"(__float_as_uint(x)), "r"(__float_as_uint(y)));
    return r;
}
__device__ __forceinline__ ull splat2(float x) { return pk2(x, x); }
__device__ __forceinline__ void upk2(ull v, float& x, float& y) {
    unsigned int a, b;
    asm("mov.b64 {%0, %1}, %2;" : "=r"(a), "=r"(b) : "l"(v));
    x = __uint_as_float(a); y = __uint_as_float(b);
}
__device__ __forceinline__ ull fma2_(ull a, ull b, ull c) {
    ull d;
    asm("fma.rn.f32x2 %0, %1, %2, %3;" : "=l"(d) : "l"(a), "l"(b), "l"(c));
    return d;
}
__device__ __forceinline__ ull mul2_(ull a, ull b) {
    ull d;
    asm("mul.rn.f32x2 %0, %1, %2;" : "=l"(d) : "l"(a), "l"(b));
    return d;
}

// ---------------- mma.sync / ldmatrix helpers (baseline sm_80+ ops) ----------------
__device__ __forceinline__ uint32_t smem_u32(const void* p) {
    uint32_t a;
    asm("{ .reg .u64 t; cvta.to.shared.u64 t, %1; cvt.u32.u64 %0, t; }" : "=r"(a) : "l"(p));
    return a;
}
__device__ __forceinline__ void ldsm4(uint32_t& r0, uint32_t& r1, uint32_t& r2, uint32_t& r3,
                                      uint32_t addr) {
    asm volatile("ldmatrix.sync.aligned.m8n8.x4.shared.b16 {%0,%1,%2,%3}, [%4];"
                 : "=r"(r0), "=r"(r1), "=r"(r2), "=r"(r3) : "r"(addr));
}
__device__ __forceinline__ void mma_bf16(float* c, uint32_t a0, uint32_t a1, uint32_t a2,
                                         uint32_t a3, uint32_t b0, uint32_t b1) {
    asm("mma.sync.aligned.m16n8k16.row.col.f32.bf16.bf16.f32 "
        "{%0,%1,%2,%3}, {%4,%5,%6,%7}, {%8,%9}, {%0,%1,%2,%3};"
        : "+f"(c[0]), "+f"(c[1]), "+f"(c[2]), "+f"(c[3])
        : "r"(a0), "r"(a1), "r"(a2), "r"(a3), "r"(b0), "r"(b1));
}

// ---------------- scratch ----------------
__device__ float g_q[Bq*Hq*Nq*HDq];
__device__ float g_k[Bq*Hq*Nq*HDq];
__device__ float g_v[Bq*Hq*Nq*HDq];
__device__ bf16 g_Xh[ROWS*Cq], g_Xl[ROWS*Cq];
__device__ bf16 g_Wth[3][Cq*Cq], g_Wtl[3][Cq*Cq];     // W^T [n][k] hi/lo
__device__ bf16 g_Wpth[Cq*Cq], g_Wptl[Cq*Cq];
__device__ bf16 g_XAh[3][ROWS*32], g_XAl[3][ROWS*32]; // bw*(x@la), rank padded to 32
__device__ bf16 g_LBh[3][Cq*32], g_LBl[3][Cq*32];     // lb^T [n][r], padded to 32
__device__ bf16 g_atth[ROWS*Cq], g_attl[ROWS*Cq];

__device__ __forceinline__ void split_bf16(float v, bf16& h, bf16& l) {
    h = __float2bfloat16(v);
    l = __float2bfloat16(v - __bfloat162float(h));
}

// ---------------- prep kernels ----------------
__global__ void convert_x_kernel(const float* __restrict__ X) {
    int i = blockIdx.x * blockDim.x + threadIdx.x;
    if (i < ROWS * Cq) {
        bf16 h, l; split_bf16(X[i], h, l);
        g_Xh[i] = h; g_Xl[i] = l;
    }
}

__global__ void transpose_w_kernel(const float* __restrict__ W, int sel) {
    __shared__ float sh[32][33];
    bf16* dh = (sel < 3) ? g_Wth[sel] : g_Wpth;
    bf16* dl = (sel < 3) ? g_Wtl[sel] : g_Wptl;
    int tx = threadIdx.x & 31, ty = threadIdx.x >> 5;
    int kb = blockIdx.y * 32, nb = blockIdx.x * 32;
    #pragma unroll
    for (int i = 0; i < 4; i++)
        sh[ty + i * 8][tx] = W[(size_t)(kb + ty + i * 8) * Cq + nb + tx];
    __syncthreads();
    #pragma unroll
    for (int i = 0; i < 4; i++) {
        float v = sh[tx][ty + i * 8];
        bf16 h, l; split_bf16(v, h, l);
        size_t idx = (size_t)(nb + ty + i * 8) * Cq + kb + tx;
        dh[idx] = h; dl[idx] = l;
    }
}

__global__ void transpose_lb_kernel(const float* __restrict__ lbq,
                                    const float* __restrict__ lbk,
                                    const float* __restrict__ lbv) {
    int idx = blockIdx.x * blockDim.x + threadIdx.x;
    if (idx >= 3 * Cq * 32) return;
    int t = idx / (Cq * 32);
    int rem = idx - t * Cq * 32;
    int n = rem >> 5, r = rem & 31;
    const float* lb = (t == 0) ? lbq : (t == 1) ? lbk : lbv;
    float v = (r < Rq) ? lb[r * Cq + n] : 0.f;
    bf16 h, l; split_bf16(v, h, l);
    g_LBh[t][n * 32 + r] = h; g_LBl[t][n * 32 + r] = l;
}

__global__ void lora_xa_kernel(const float* __restrict__ X,
                               const float* __restrict__ la_q,
                               const float* __restrict__ la_k,
                               const float* __restrict__ la_v,
                               const float* __restrict__ bw) {
    __shared__ float xs[16][Cq];
    int rowBase = blockIdx.x * 16;
    for (int l = threadIdx.x; l < 16 * Cq; l += 256) {
        int r = l / Cq, c = l % Cq;
        xs[r][c] = X[(size_t)(rowBase + r) * Cq + c];
    }
    __syncthreads();
    int r = threadIdx.x >> 4;
    int c = threadIdx.x & 15;
    float aq = 0.f, ak = 0.f, av = 0.f;
    #pragma unroll 4
    for (int k = 0; k < Cq; k++) {
        float xv = xs[r][k];
        aq = fmaf(xv, la_q[k * Rq + c], aq);
        ak = fmaf(xv, la_k[k * Rq + c], ak);
        av = fmaf(xv, la_v[k * Rq + c], av);
    }
    int row = rowBase + r;
    bf16 h, l;
    split_bf16(bw[0] * aq, h, l); g_XAh[0][row * 32 + c] = h; g_XAl[0][row * 32 + c] = l;
    split_bf16(bw[1] * ak, h, l); g_XAh[1][row * 32 + c] = h; g_XAl[1][row * 32 + c] = l;
    split_bf16(bw[2] * av, h, l); g_XAh[2][row * 32 + c] = h; g_XAl[2][row * 32 + c] = l;
    for (int l2 = threadIdx.x; l2 < 16 * 16; l2 += 256) {
        int rr = l2 >> 4, cc = 16 + (l2 & 15);
        int rowz = rowBase + rr;
        #pragma unroll
        for (int t = 0; t < 3; t++) {
            g_XAh[t][rowz * 32 + cc] = __float2bfloat16(0.f);
            g_XAl[t][rowz * 32 + cc] = __float2bfloat16(0.f);
        }
    }
}

// ---------------- shared GEMM core: 128x128 tile, K-chunks of 32, bf16 mma 3-pass ----------------
#define APITCH 40          // 128 rows x 40 bf16 = 80B rows: conflict-free for ldmatrix

struct GemmSmem {
    bf16 Ah[128 * APITCH];
    bf16 Al[128 * APITCH];
    bf16 Bh[128 * APITCH];
    bf16 Bl[128 * APITCH];
};

__device__ __forceinline__ void load_tile32(bf16* dst, const bf16* __restrict__ src,
                                            int stride, int tid) {
    #pragma unroll
    for (int i = 0; i < 2; i++) {
        int idx = tid + 256 * i;
        int row = idx >> 2, seg = idx & 3;
        *(uint4*)&dst[row * APITCH + seg * 8] = *(const uint4*)(src + (size_t)row * stride + seg * 8);
    }
}

// Computes 128x128 C-tile accumulated over chunks; warp layout 4x2 (32m x 64n each).
// nchunks: number of 32-wide K chunks; getptr callback pattern replaced by arrays.
struct ChunkSrc { const bf16 *ah, *al, *bh, *bl; int stride; };

__device__ __forceinline__ void gemm_core(GemmSmem* s, float C[2][8][4],
                                          int tid, int nchunks,
                                          const ChunkSrc* make, // array in regs? no: computed by caller loop
                                          int dummy) {}

// ---------------- qkv GEMM with fused LoRA chunk ----------------
__global__ __launch_bounds__(256) void gemm_qkv_kernel() {
    __shared__ GemmSmem s;
    int tid = threadIdx.x, lid = tid & 31, wid = tid >> 5;
    int wm = (wid & 3) * 32, wn = (wid >> 2) * 64;
    int type = blockIdx.z;
    int rowBase = blockIdx.y * 128, colBase = blockIdx.x * 128;

    const bf16* Xh = g_Xh + (size_t)rowBase * Cq;
    const bf16* Xl = g_Xl + (size_t)rowBase * Cq;
    const bf16* Wh = g_Wth[type] + (size_t)colBase * Cq;
    const bf16* Wl = g_Wtl[type] + (size_t)colBase * Cq;

    float C[2][8][4];
    #pragma unroll
    for (int i = 0; i < 2; i++)
        #pragma unroll
        for (int j = 0; j < 8; j++)
            #pragma unroll
            for (int k = 0; k < 4; k++) C[i][j][k] = 0.f;

    // ldmatrix lane address offsets (in elements)
    uint32_t aBaseH = smem_u32(s.Ah), aBaseL = smem_u32(s.Al);
    uint32_t bBaseH = smem_u32(s.Bh), bBaseL = smem_u32(s.Bl);
    int a_off = (wm + (lid & 15)) * APITCH + ((lid >> 4) & 1) * 8;
    int b_off = (wn + ((lid >> 4) & 1) * 8 + (lid & 7)) * APITCH + ((lid >> 3) & 1) * 8;

    for (int c = 0; c < 25; c++) {
        if (c < 24) {
            load_tile32(s.Ah, Xh + c * 32, Cq, tid);
            load_tile32(s.Al, Xl + c * 32, Cq, tid);
            load_tile32(s.Bh, Wh + c * 32, Cq, tid);
            load_tile32(s.Bl, Wl + c * 32, Cq, tid);
        } else {
            load_tile32(s.Ah, g_XAh[type] + (size_t)rowBase * 32, 32, tid);
            load_tile32(s.Al, g_XAl[type] + (size_t)rowBase * 32, 32, tid);
            load_tile32(s.Bh, g_LBh[type] + (size_t)colBase * 32, 32, tid);
            load_tile32(s.Bl, g_LBl[type] + (size_t)colBase * 32, 32, tid);
        }
        __syncthreads();
        int nkt = (c < 24) ? 2 : 1;   // LoRA rank 16 lives in first k16 only
        for (int kt = 0; kt < nkt; kt++) {
            int ko = kt * 16;
            uint32_t ah[2][4], al[2][4], bh[8][2], bl[8][2];
            #pragma unroll
            for (int mt = 0; mt < 2; mt++) {
                int off = (a_off + mt * 16 * APITCH + ko) * 2;
                ldsm4(ah[mt][0], ah[mt][1], ah[mt][2], ah[mt][3], aBaseH + off);
                ldsm4(al[mt][0], al[mt][1], al[mt][2], al[mt][3], aBaseL + off);
            }
            #pragma unroll
            for (int p = 0; p < 4; p++) {
                int off = (b_off + p * 16 * APITCH + ko) * 2;
                ldsm4(bh[2*p][0], bh[2*p][1], bh[2*p+1][0], bh[2*p+1][1], bBaseH + off);
                ldsm4(bl[2*p][0], bl[2*p][1], bl[2*p+1][0], bl[2*p+1][1], bBaseL + off);
            }
            #pragma unroll
            for (int mt = 0; mt < 2; mt++)
                #pragma unroll
                for (int nt = 0; nt < 8; nt++) {
                    mma_bf16(C[mt][nt], ah[mt][0], ah[mt][1], ah[mt][2], ah[mt][3],
                             bh[nt][0], bh[nt][1]);
                    mma_bf16(C[mt][nt], ah[mt][0], ah[mt][1], ah[mt][2], ah[mt][3],
                             bl[nt][0], bl[nt][1]);
                    mma_bf16(C[mt][nt], al[mt][0], al[mt][1], al[mt][2], al[mt][3],
                             bh[nt][0], bh[nt][1]);
                }
        }
        __syncthreads();
    }

    // epilogue -> head-split [B,H,N,HD]
    float* out = (type == 0) ? g_q : (type == 1) ? g_k : g_v;
    #pragma unroll
    for (int mt = 0; mt < 2; mt++)
        #pragma unroll
        for (int nt = 0; nt < 8; nt++) {
            int col = colBase + wn + nt * 8 + (lid & 3) * 2;
            int h = col >> 6, hd = col & 63;
            #pragma unroll
            for (int half = 0; half < 2; half++) {
                int row = rowBase + wm + mt * 16 + (lid >> 2) + half * 8;
                int b_ = row >> 10, n = row & 1023;
                float2 v = make_float2(C[mt][nt][half * 2], C[mt][nt][half * 2 + 1]);
                *(float2*)&out[(((size_t)(b_ * Hq + h) * Nq) + n) * HDq + hd] = v;
            }
        }
}

// ---------------- output projection GEMM + bias ----------------
__global__ __launch_bounds__(256) void gemm_out_kernel(const float* __restrict__ bias,
                                                       float* __restrict__ out) {
    __shared__ GemmSmem s;
    int tid = threadIdx.x, lid = tid & 31, wid = tid >> 5;
    int wm = (wid & 3) * 32, wn = (wid >> 2) * 64;
    int rowBase = blockIdx.y * 128, colBase = blockIdx.x * 128;

    const bf16* Ah = g_atth + (size_t)rowBase * Cq;
    const bf16* Al = g_attl + (size_t)rowBase * Cq;
    const bf16* Wh = g_Wpth + (size_t)colBase * Cq;
    const bf16* Wl = g_Wptl + (size_t)colBase * Cq;

    float C[2][8][4];
    #pragma unroll
    for (int i = 0; i < 2; i++)
        #pragma unroll
        for (int j = 0; j < 8; j++)
            #pragma unroll
            for (int k = 0; k < 4; k++) C[i][j][k] = 0.f;

    uint32_t aBaseH = smem_u32(s.Ah), aBaseL = smem_u32(s.Al);
    uint32_t bBaseH = smem_u32(s.Bh), bBaseL = smem_u32(s.Bl);
    int a_off = (wm + (lid & 15)) * APITCH + ((lid >> 4) & 1) * 8;
    int b_off = (wn + ((lid >> 4) & 1) * 8 + (lid & 7)) * APITCH + ((lid >> 3) & 1) * 8;

    for (int c = 0; c < 24; c++) {
        load_tile32(s.Ah, Ah + c * 32, Cq, tid);
        load_tile32(s.Al, Al + c * 32, Cq, tid);
        load_tile32(s.Bh, Wh + c * 32, Cq, tid);
        load_tile32(s.Bl, Wl + c * 32, Cq, tid);
        __syncthreads();
        #pragma unroll
        for (int kt = 0; kt < 2; kt++) {
            int ko = kt * 16;
            uint32_t ah[2][4], al[2][4], bh[8][2], bl[8][2];
            #pragma unroll
            for (int mt = 0; mt < 2; mt++) {
                int off = (a_off + mt * 16 * APITCH + ko) * 2;
                ldsm4(ah[mt][0], ah[mt][1], ah[mt][2], ah[mt][3], aBaseH + off);
                ldsm4(al[mt][0], al[mt][1], al[mt][2], al[mt][3], aBaseL + off);
            }
            #pragma unroll
            for (int p = 0; p < 4; p++) {
                int off = (b_off + p * 16 * APITCH + ko) * 2;
                ldsm4(bh[2*p][0], bh[2*p][1], bh[2*p+1][0], bh[2*p+1][1], bBaseH + off);
                ldsm4(bl[2*p][0], bl[2*p][1], bl[2*p+1][0], bl[2*p+1][1], bBaseL + off);
            }
            #pragma unroll
            for (int mt = 0; mt < 2; mt++)
                #pragma unroll
                for (int nt = 0; nt < 8; nt++) {
                    mma_bf16(C[mt][nt], ah[mt][0], ah[mt][1], ah[mt][2], ah[mt][3],
                             bh[nt][0], bh[nt][1]);
                    mma_bf16(C[mt][nt], ah[mt][0], ah[mt][1], ah[mt][2], ah[mt][3],
                             bl[nt][0], bl[nt][1]);
                    mma_bf16(C[mt][nt], al[mt][0], al[mt][1], al[mt][2], al[mt][3],
                             bh[nt][0], bh[nt][1]);
                }
        }
        __syncthreads();
    }

    #pragma unroll
    for (int mt = 0; mt < 2; mt++)
        #pragma unroll
        for (int nt = 0; nt < 8; nt++) {
            int col = colBase + wn + nt * 8 + (lid & 3) * 2;
            float2 bv = *(const float2*)&bias[col];
            #pragma unroll
            for (int half = 0; half < 2; half++) {
                int row = rowBase + wm + mt * 16 + (lid >> 2) + half * 8;
                float2 v = make_float2(C[mt][nt][half * 2] + bv.x, C[mt][nt][half * 2 + 1] + bv.y);
                *(float2*)&out[(size_t)row * Cq + col] = v;
            }
        }
}

// ---------------- flash attention (SIMT f32x2), epilogue -> bf16 hi/lo ----------------
#define SP 132
#define VP 68

__global__ __launch_bounds__(256, 1) void attn_kernel() {
    extern __shared__ float sm[];
    float* Qs   = sm;
    float* Ks   = Qs + 64 * SP;
    float* Vs   = Ks + 64 * SP;
    float* Ss   = Vs + 128 * VP;
    float* mrow = Ss + 128 * SP;
    float* lrow = mrow + 128;
    float* arow = lrow + 128;

    int tid = threadIdx.x;
    int tx = tid & 15, ty = tid >> 4;
    int qt = blockIdx.x;
    int h = blockIdx.y, b = blockIdx.z;
    const float* Qg = g_q + ((size_t)(b * Hq + h) * Nq + qt * 128) * HDq;
    const float* Kg = g_k + (size_t)(b * Hq + h) * Nq * HDq;
    const float* Vg = g_v + (size_t)(b * Hq + h) * Nq * HDq;

    for (int l = tid; l < 128 * 64; l += 256) {
        int m = l >> 6, c = l & 63;
        Qs[c * SP + m] = Qg[m * HDq + c];
    }
    if (tid < 128) { mrow[tid] = -1e30f; lrow[tid] = 0.f; }

    ull op[4][4] = {};
    const ull sc2 = splat2(SCALE);

    for (int kt = 0; kt < Nq / 128; kt++) {
        __syncthreads();
        for (int l = tid; l < 128 * 64; l += 256) {
            int j = l >> 6, c = l & 63;
            Ks[c * SP + j] = Kg[(kt * 128 + j) * HDq + c];
            Vs[j * VP + c] = Vg[(kt * 128 + j) * HDq + c];
        }
        __syncthreads();
        {
            ull sp[8][4] = {};
            #pragma unroll 4
            for (int k = 0; k < HDq; k++) {
                float4 k0v = *(const float4*)&Ks[k * SP + tx * 8];
                float4 k1v = *(const float4*)&Ks[k * SP + tx * 8 + 4];
                ulonglong2 q0 = *(const ulonglong2*)&Qs[k * SP + ty * 8];
                ulonglong2 q1 = *(const ulonglong2*)&Qs[k * SP + ty * 8 + 4];
                ull qp[4] = {q0.x, q0.y, q1.x, q1.y};
                float kv[8] = {k0v.x, k0v.y, k0v.z, k0v.w, k1v.x, k1v.y, k1v.z, k1v.w};
                #pragma unroll
                for (int jj = 0; jj < 8; jj++) {
                    ull kk2 = splat2(kv[jj]);
                    #pragma unroll
                    for (int ip = 0; ip < 4; ip++)
                        sp[jj][ip] = fma2_(kk2, qp[ip], sp[jj][ip]);
                }
            }
            #pragma unroll
            for (int jj = 0; jj < 8; jj++)
                #pragma unroll
                for (int ip = 0; ip < 4; ip++)
                    *(ull*)&Ss[(tx * 8 + jj) * SP + ty * 8 + ip * 2] = mul2_(sp[jj][ip], sc2);
        }
        __syncthreads();
        {
            int row = tid >> 1, half = tid & 1;
            int jb = half * 64;
            float mx = -1e30f;
            #pragma unroll 8
            for (int j2 = 0; j2 < 64; j2++)
                mx = fmaxf(mx, Ss[(jb + j2) * SP + row]);
            mx = fmaxf(mx, __shfl_xor_sync(0xffffffffu, mx, 1));
            float mprev = mrow[row];
            float mnew = fmaxf(mprev, mx);
            float sum = 0.f;
            #pragma unroll 8
            for (int j2 = 0; j2 < 64; j2++) {
                float p = __expf(Ss[(jb + j2) * SP + row] - mnew);
                Ss[(jb + j2) * SP + row] = p;
                sum += p;
            }
            sum += __shfl_xor_sync(0xffffffffu, sum, 1);
            if (half == 0) {
                float al = __expf(mprev - mnew);
                mrow[row] = mnew;
                lrow[row] = lrow[row] * al + sum;
                arow[row] = al;
            }
        }
        __syncthreads();
        {
            #pragma unroll
            for (int mp = 0; mp < 4; mp++) {
                ull ap = *(const ull*)&arow[ty * 8 + mp * 2];
                #pragma unroll
                for (int nc = 0; nc < 4; nc++)
                    op[nc][mp] = mul2_(op[nc][mp], ap);
            }
            #pragma unroll 2
            for (int j = 0; j < 128; j++) {
                float4 vv = *(const float4*)&Vs[j * VP + tx * 4];
                ulonglong2 p0 = *(const ulonglong2*)&Ss[j * SP + ty * 8];
                ulonglong2 p1 = *(const ulonglong2*)&Ss[j * SP + ty * 8 + 4];
                ull pf[4] = {p0.x, p0.y, p1.x, p1.y};
                float va[4] = {vv.x, vv.y, vv.z, vv.w};
                #pragma unroll
                for (int nc = 0; nc < 4; nc++) {
                    ull v2 = splat2(va[nc]);
                    #pragma unroll
                    for (int mp = 0; mp < 4; mp++)
                        op[nc][mp] = fma2_(v2, pf[mp], op[nc][mp]);
                }
            }
        }
    }
    __syncthreads();

    float inv[8];
    #pragma unroll
    for (int r = 0; r < 8; r++) inv[r] = 1.f / lrow[ty * 8 + r];
    #pragma unroll
    for (int nc = 0; nc < 4; nc++) {
        int col = h * HDq + tx * 4 + nc;
        #pragma unroll
        for (int mp = 0; mp < 4; mp++) {
            float o0, o1;
            upk2(op[nc][mp], o0, o1);
            int m0 = ty * 8 + mp * 2;
            size_t row0 = (size_t)b * Nq + qt * 128 + m0;
            float a0 = o0 * inv[mp * 2], a1 = o1 * inv[mp * 2 + 1];
            bf16 hh, ll;
            split_bf16(a0, hh, ll);
            g_atth[row0 * Cq + col] = hh; g_attl[row0 * Cq + col] = ll;
            split_bf16(a1, hh, ll);
            g_atth[(row0 + 1) * Cq + col] = hh; g_attl[(row0 + 1) * Cq + col] = ll;
        }
    }
}

extern "C" void kernel_launch(void* const* d_in, const int* in_sizes, int n_in,
                              void* d_out, int out_size) {
    const float* x    = (const float*)d_in[0];
    const float* Wq   = (const float*)d_in[1];
    const float* Wk   = (const float*)d_in[2];
    const float* Wv   = (const float*)d_in[3];
    const float* Wp   = (const float*)d_in[4];
    const float* bp   = (const float*)d_in[5];
    const float* la_q = (const float*)d_in[6];
    const float* lb_q = (const float*)d_in[7];
    const float* la_k = (const float*)d_in[8];
    const float* lb_k = (const float*)d_in[9];
    const float* la_v = (const float*)d_in[10];
    const float* lb_v = (const float*)d_in[11];
    const float* bw   = (const float*)d_in[12];
    float* out = (float*)d_out;

    convert_x_kernel<<<(ROWS * Cq + 255) / 256, 256>>>(x);
    dim3 gt(24, 24);
    transpose_w_kernel<<<gt, 256>>>(Wq, 0);
    transpose_w_kernel<<<gt, 256>>>(Wk, 1);
    transpose_w_kernel<<<gt, 256>>>(Wv, 2);
    transpose_w_kernel<<<gt, 256>>>(Wp, 3);
    transpose_lb_kernel<<<(3 * Cq * 32 + 255) / 256, 256>>>(lb_q, lb_k, lb_v);
    lora_xa_kernel<<<ROWS / 16, 256>>>(x, la_q, la_k, la_v, bw);

    gemm_qkv_kernel<<<dim3(6, 64, 3), 256>>>();

    size_t smem = (size_t)(64 * SP + 64 * SP + 128 * VP + 128 * SP + 3 * 128) * sizeof(float);
    cudaFuncSetAttribute(attn_kernel, cudaFuncAttributeMaxDynamicSharedMemorySize, (int)smem);
    attn_kernel<<<dim3(Nq / 128, Hq, Bq), 256, smem>>>();

    gemm_out_kernel<<<dim3(6, 64), 256>>>(bp, out);
}

// round 5
// speedup vs baseline: 1.5812x; 1.5812x over previous
#include <cuda_runtime.h>
#include <cuda_bf16.h>
#include <cstdint>

#define Bq 8
#define Nq 1024
#define Cq 768
#define Hq 12
#define HDq 64
#define Rq 16
#define ROWS (Bq*Nq)
#define SCALE 0.125f

typedef unsigned long long ull;
typedef __nv_bfloat16 bf16;

// ---------------- f32x2 helpers ----------------
__device__ __forceinline__ ull pk2(float x, float y) {
    ull r;
    asm("mov.b64 %0, {%1, %2};" : "=l"(r) : "r"(__float_as_uint(x)), "r"(__float_as_uint(y)));
    return r;
}
__device__ __forceinline__ ull splat2(float x) { return pk2(x, x); }
__device__ __forceinline__ void upk2(ull v, float& x, float& y) {
    unsigned int a, b;
    asm("mov.b64 {%0, %1}, %2;" : "=r"(a), "=r"(b) : "l"(v));
    x = __uint_as_float(a); y = __uint_as_float(b);
}
__device__ __forceinline__ ull fma2_(ull a, ull b, ull c) {
    ull d;
    asm("fma.rn.f32x2 %0, %1, %2, %3;" : "=l"(d) : "l"(a), "l"(b), "l"(c));
    return d;
}
__device__ __forceinline__ ull mul2_(ull a, ull b) {
    ull d;
    asm("mul.rn.f32x2 %0, %1, %2;" : "=l"(d) : "l"(a), "l"(b));
    return d;
}

// ---------------- mma.sync / ldmatrix / cp.async helpers ----------------
__device__ __forceinline__ uint32_t smem_u32(const void* p) {
    uint32_t a;
    asm("{ .reg .u64 t; cvta.to.shared.u64 t, %1; cvt.u32.u64 %0, t; }" : "=r"(a) : "l"(p));
    return a;
}
__device__ __forceinline__ void ldsm4(uint32_t& r0, uint32_t& r1, uint32_t& r2, uint32_t& r3,
                                      uint32_t addr) {
    asm volatile("ldmatrix.sync.aligned.m8n8.x4.shared.b16 {%0,%1,%2,%3}, [%4];"
                 : "=r"(r0), "=r"(r1), "=r"(r2), "=r"(r3) : "r"(addr));
}
__device__ __forceinline__ void mma_bf16(float* c, uint32_t a0, uint32_t a1, uint32_t a2,
                                         uint32_t a3, uint32_t b0, uint32_t b1) {
    asm("mma.sync.aligned.m16n8k16.row.col.f32.bf16.bf16.f32 "
        "{%0,%1,%2,%3}, {%4,%5,%6,%7}, {%8,%9}, {%0,%1,%2,%3};"
        : "+f"(c[0]), "+f"(c[1]), "+f"(c[2]), "+f"(c[3])
        : "r"(a0), "r"(a1), "r"(a2), "r"(a3), "r"(b0), "r"(b1));
}
__device__ __forceinline__ void cp16(uint32_t dst, const void* src) {
    asm volatile("cp.async.cg.shared.global [%0], [%1], 16;" :: "r"(dst), "l"(src));
}
__device__ __forceinline__ void cp_commit() {
    asm volatile("cp.async.commit_group;" ::: "memory");
}
template <int N>
__device__ __forceinline__ void cp_wait() {
    asm volatile("cp.async.wait_group %0;" :: "n"(N) : "memory");
}

// ---------------- scratch ----------------
__device__ float g_q[Bq*Hq*Nq*HDq];
__device__ float g_k[Bq*Hq*Nq*HDq];
__device__ float g_v[Bq*Hq*Nq*HDq];
__device__ bf16 g_Xh[ROWS*Cq], g_Xl[ROWS*Cq];
__device__ bf16 g_Wth[3][Cq*Cq], g_Wtl[3][Cq*Cq];
__device__ bf16 g_Wpth[Cq*Cq], g_Wptl[Cq*Cq];
__device__ bf16 g_XAh[3][ROWS*32], g_XAl[3][ROWS*32];
__device__ bf16 g_LBh[3][Cq*32], g_LBl[3][Cq*32];
__device__ bf16 g_atth[ROWS*Cq], g_attl[ROWS*Cq];

__device__ __forceinline__ void split_bf16(float v, bf16& h, bf16& l) {
    h = __float2bfloat16(v);
    l = __float2bfloat16(v - __bfloat162float(h));
}

// ---------------- prep kernels ----------------
__global__ void convert_x_kernel(const float* __restrict__ X) {
    int i = blockIdx.x * blockDim.x + threadIdx.x;
    if (i < ROWS * Cq) {
        bf16 h, l; split_bf16(X[i], h, l);
        g_Xh[i] = h; g_Xl[i] = l;
    }
}

__global__ void transpose_w_kernel(const float* __restrict__ Wq_, const float* __restrict__ Wk_,
                                   const float* __restrict__ Wv_, const float* __restrict__ Wp_) {
    __shared__ float sh[32][33];
    int sel = blockIdx.z;
    const float* W = (sel == 0) ? Wq_ : (sel == 1) ? Wk_ : (sel == 2) ? Wv_ : Wp_;
    bf16* dh = (sel < 3) ? g_Wth[sel] : g_Wpth;
    bf16* dl = (sel < 3) ? g_Wtl[sel] : g_Wptl;
    int tx = threadIdx.x & 31, ty = threadIdx.x >> 5;
    int kb = blockIdx.y * 32, nb = blockIdx.x * 32;
    #pragma unroll
    for (int i = 0; i < 4; i++)
        sh[ty + i * 8][tx] = W[(size_t)(kb + ty + i * 8) * Cq + nb + tx];
    __syncthreads();
    #pragma unroll
    for (int i = 0; i < 4; i++) {
        float v = sh[tx][ty + i * 8];
        bf16 h, l; split_bf16(v, h, l);
        size_t idx = (size_t)(nb + ty + i * 8) * Cq + kb + tx;
        dh[idx] = h; dl[idx] = l;
    }
}

__global__ void transpose_lb_kernel(const float* __restrict__ lbq,
                                    const float* __restrict__ lbk,
                                    const float* __restrict__ lbv) {
    int idx = blockIdx.x * blockDim.x + threadIdx.x;
    if (idx >= 3 * Cq * 32) return;
    int t = idx / (Cq * 32);
    int rem = idx - t * Cq * 32;
    int n = rem >> 5, r = rem & 31;
    const float* lb = (t == 0) ? lbq : (t == 1) ? lbk : lbv;
    float v = (r < Rq) ? lb[r * Cq + n] : 0.f;
    bf16 h, l; split_bf16(v, h, l);
    g_LBh[t][n * 32 + r] = h; g_LBl[t][n * 32 + r] = l;
}

__global__ void lora_xa_kernel(const float* __restrict__ X,
                               const float* __restrict__ la_q,
                               const float* __restrict__ la_k,
                               const float* __restrict__ la_v,
                               const float* __restrict__ bw) {
    __shared__ float xs[16][Cq];
    int rowBase = blockIdx.x * 16;
    for (int l = threadIdx.x; l < 16 * Cq; l += 256) {
        int r = l / Cq, c = l % Cq;
        xs[r][c] = X[(size_t)(rowBase + r) * Cq + c];
    }
    __syncthreads();
    int r = threadIdx.x >> 4;
    int c = threadIdx.x & 15;
    float aq = 0.f, ak = 0.f, av = 0.f;
    #pragma unroll 4
    for (int k = 0; k < Cq; k++) {
        float xv = xs[r][k];
        aq = fmaf(xv, la_q[k * Rq + c], aq);
        ak = fmaf(xv, la_k[k * Rq + c], ak);
        av = fmaf(xv, la_v[k * Rq + c], av);
    }
    int row = rowBase + r;
    bf16 h, l;
    split_bf16(bw[0] * aq, h, l); g_XAh[0][row * 32 + c] = h; g_XAl[0][row * 32 + c] = l;
    split_bf16(bw[1] * ak, h, l); g_XAh[1][row * 32 + c] = h; g_XAl[1][row * 32 + c] = l;
    split_bf16(bw[2] * av, h, l); g_XAh[2][row * 32 + c] = h; g_XAl[2][row * 32 + c] = l;
    for (int l2 = threadIdx.x; l2 < 16 * 16; l2 += 256) {
        int rr = l2 >> 4, cc = 16 + (l2 & 15);
        int rowz = rowBase + rr;
        #pragma unroll
        for (int t = 0; t < 3; t++) {
            g_XAh[t][rowz * 32 + cc] = __float2bfloat16(0.f);
            g_XAl[t][rowz * 32 + cc] = __float2bfloat16(0.f);
        }
    }
}

// ---------------- pipelined bf16 GEMM core ----------------
#define PITCH 40
#define NSTAGE 4
#define TILE_B 10240                       // 128*PITCH*2 bytes
#define STAGE_B (4*TILE_B)                 // Ah,Al,Bh,Bl
#define GEMM_DSMEM (NSTAGE*STAGE_B)        // 160KB

// issue one chunk's 4 tiles as cp.async (8 x 16B per thread)
__device__ __forceinline__ void issue_chunk(uint32_t sbase, int stage,
                                            const bf16* ah, const bf16* al,
                                            const bf16* bh, const bf16* bl,
                                            int stride, int tid) {
    uint32_t st = sbase + stage * STAGE_B;
    const bf16* srcs[4] = {ah, al, bh, bl};
    #pragma unroll
    for (int t = 0; t < 4; t++) {
        #pragma unroll
        for (int i = 0; i < 2; i++) {
            int idx = tid + 256 * i;
            int row = idx >> 2, seg = idx & 3;
            cp16(st + t * TILE_B + (row * PITCH + seg * 8) * 2,
                 srcs[t] + (size_t)row * stride + seg * 8);
        }
    }
    cp_commit();
}

// compute one 32-wide K chunk (2 x k16), 3-pass hi/lo
__device__ __forceinline__ void compute_chunk(uint32_t sbase, int stage,
                                              float C[2][8][4], int a_off, int b_off) {
    uint32_t st = sbase + stage * STAGE_B;
    uint32_t aH = st, aL = st + TILE_B, bH = st + 2 * TILE_B, bL = st + 3 * TILE_B;
    #pragma unroll
    for (int kt = 0; kt < 2; kt++) {
        int ko = kt * 16;
        uint32_t ah[2][4], al[2][4], bh[8][2], bl[8][2];
        #pragma unroll
        for (int mt = 0; mt < 2; mt++) {
            int off = (a_off + mt * 16 * PITCH + ko) * 2;
            ldsm4(ah[mt][0], ah[mt][1], ah[mt][2], ah[mt][3], aH + off);
            ldsm4(al[mt][0], al[mt][1], al[mt][2], al[mt][3], aL + off);
        }
        #pragma unroll
        for (int p = 0; p < 4; p++) {
            int off = (b_off + p * 16 * PITCH + ko) * 2;
            ldsm4(bh[2*p][0], bh[2*p][1], bh[2*p+1][0], bh[2*p+1][1], bH + off);
            ldsm4(bl[2*p][0], bl[2*p][1], bl[2*p+1][0], bl[2*p+1][1], bL + off);
        }
        #pragma unroll
        for (int mt = 0; mt < 2; mt++)
            #pragma unroll
            for (int nt = 0; nt < 8; nt++) {
                mma_bf16(C[mt][nt], ah[mt][0], ah[mt][1], ah[mt][2], ah[mt][3],
                         bh[nt][0], bh[nt][1]);
                mma_bf16(C[mt][nt], ah[mt][0], ah[mt][1], ah[mt][2], ah[mt][3],
                         bl[nt][0], bl[nt][1]);
                mma_bf16(C[mt][nt], al[mt][0], al[mt][1], al[mt][2], al[mt][3],
                         bh[nt][0], bh[nt][1]);
            }
    }
}

// ---------------- qkv GEMM (25 chunks: 24 main + 1 LoRA) ----------------
__global__ __launch_bounds__(256) void gemm_qkv_kernel() {
    extern __shared__ char dsm[];
    uint32_t sbase = smem_u32(dsm);
    int tid = threadIdx.x, lid = tid & 31, wid = tid >> 5;
    int wm = (wid & 3) * 32, wn = (wid >> 2) * 64;
    int type = blockIdx.z;
    int rowBase = blockIdx.y * 128, colBase = blockIdx.x * 128;

    const bf16* Xh = g_Xh + (size_t)rowBase * Cq;
    const bf16* Xl = g_Xl + (size_t)rowBase * Cq;
    const bf16* Wh = g_Wth[type] + (size_t)colBase * Cq;
    const bf16* Wl = g_Wtl[type] + (size_t)colBase * Cq;
    const bf16* XAh = g_XAh[type] + (size_t)rowBase * 32;
    const bf16* XAl = g_XAl[type] + (size_t)rowBase * 32;
    const bf16* LBh = g_LBh[type] + (size_t)colBase * 32;
    const bf16* LBl = g_LBl[type] + (size_t)colBase * 32;

    float C[2][8][4];
    #pragma unroll
    for (int i = 0; i < 2; i++)
        #pragma unroll
        for (int j = 0; j < 8; j++)
            #pragma unroll
            for (int k = 0; k < 4; k++) C[i][j][k] = 0.f;

    int a_off = (wm + (lid & 15)) * PITCH + ((lid >> 4) & 1) * 8;
    int b_off = (wn + ((lid >> 4) & 1) * 8 + (lid & 7)) * PITCH + ((lid >> 3) & 1) * 8;

    const int NCH = 25;
    // prologue: stages 0..NSTAGE-2
    #pragma unroll
    for (int s = 0; s < NSTAGE - 1; s++) {
        if (s < 24)
            issue_chunk(sbase, s, Xh + s * 32, Xl + s * 32, Wh + s * 32, Wl + s * 32, Cq, tid);
        else
            issue_chunk(sbase, s, XAh, XAl, LBh, LBl, 32, tid);
    }
    for (int c = 0; c < NCH; c++) {
        cp_wait<NSTAGE - 2>();
        __syncthreads();
        int nc = c + NSTAGE - 1;
        if (nc < NCH) {
            int st = nc & (NSTAGE - 1);
            if (nc < 24)
                issue_chunk(sbase, st, Xh + nc * 32, Xl + nc * 32, Wh + nc * 32, Wl + nc * 32, Cq, tid);
            else
                issue_chunk(sbase, st, XAh, XAl, LBh, LBl, 32, tid);
        } else {
            cp_commit();   // empty group keeps wait_group counting uniform
        }
        compute_chunk(sbase, c & (NSTAGE - 1), C, a_off, b_off);
    }

    float* out = (type == 0) ? g_q : (type == 1) ? g_k : g_v;
    #pragma unroll
    for (int mt = 0; mt < 2; mt++)
        #pragma unroll
        for (int nt = 0; nt < 8; nt++) {
            int col = colBase + wn + nt * 8 + (lid & 3) * 2;
            int h = col >> 6, hd = col & 63;
            #pragma unroll
            for (int half = 0; half < 2; half++) {
                int row = rowBase + wm + mt * 16 + (lid >> 2) + half * 8;
                int b_ = row >> 10, n = row & 1023;
                float2 v = make_float2(C[mt][nt][half * 2], C[mt][nt][half * 2 + 1]);
                *(float2*)&out[(((size_t)(b_ * Hq + h) * Nq) + n) * HDq + hd] = v;
            }
        }
}

// ---------------- output projection GEMM + bias (24 chunks) ----------------
__global__ __launch_bounds__(256) void gemm_out_kernel(const float* __restrict__ bias,
                                                       float* __restrict__ out) {
    extern __shared__ char dsm[];
    uint32_t sbase = smem_u32(dsm);
    int tid = threadIdx.x, lid = tid & 31, wid = tid >> 5;
    int wm = (wid & 3) * 32, wn = (wid >> 2) * 64;
    int rowBase = blockIdx.y * 128, colBase = blockIdx.x * 128;

    const bf16* Ah = g_atth + (size_t)rowBase * Cq;
    const bf16* Al = g_attl + (size_t)rowBase * Cq;
    const bf16* Wh = g_Wpth + (size_t)colBase * Cq;
    const bf16* Wl = g_Wptl + (size_t)colBase * Cq;

    float C[2][8][4];
    #pragma unroll
    for (int i = 0; i < 2; i++)
        #pragma unroll
        for (int j = 0; j < 8; j++)
            #pragma unroll
            for (int k = 0; k < 4; k++) C[i][j][k] = 0.f;

    int a_off = (wm + (lid & 15)) * PITCH + ((lid >> 4) & 1) * 8;
    int b_off = (wn + ((lid >> 4) & 1) * 8 + (lid & 7)) * PITCH + ((lid >> 3) & 1) * 8;

    const int NCH = 24;
    #pragma unroll
    for (int s = 0; s < NSTAGE - 1; s++)
        issue_chunk(sbase, s, Ah + s * 32, Al + s * 32, Wh + s * 32, Wl + s * 32, Cq, tid);
    for (int c = 0; c < NCH; c++) {
        cp_wait<NSTAGE - 2>();
        __syncthreads();
        int nc = c + NSTAGE - 1;
        if (nc < NCH)
            issue_chunk(sbase, nc & (NSTAGE - 1), Ah + nc * 32, Al + nc * 32,
                        Wh + nc * 32, Wl + nc * 32, Cq, tid);
        else
            cp_commit();
        compute_chunk(sbase, c & (NSTAGE - 1), C, a_off, b_off);
    }

    #pragma unroll
    for (int mt = 0; mt < 2; mt++)
        #pragma unroll
        for (int nt = 0; nt < 8; nt++) {
            int col = colBase + wn + nt * 8 + (lid & 3) * 2;
            float2 bv = *(const float2*)&bias[col];
            #pragma unroll
            for (int half = 0; half < 2; half++) {
                int row = rowBase + wm + mt * 16 + (lid >> 2) + half * 8;
                float2 v = make_float2(C[mt][nt][half * 2] + bv.x, C[mt][nt][half * 2 + 1] + bv.y);
                *(float2*)&out[(size_t)row * Cq + col] = v;
            }
        }
}

// ---------------- flash attention (SIMT f32x2), epilogue -> bf16 hi/lo ----------------
#define SP 132
#define VP 68

__global__ __launch_bounds__(256, 1) void attn_kernel() {
    extern __shared__ float sm[];
    float* Qs   = sm;
    float* Ks   = Qs + 64 * SP;
    float* Vs   = Ks + 64 * SP;
    float* Ss   = Vs + 128 * VP;
    float* mrow = Ss + 128 * SP;
    float* lrow = mrow + 128;
    float* arow = lrow + 128;

    int tid = threadIdx.x;
    int tx = tid & 15, ty = tid >> 4;
    int qt = blockIdx.x;
    int h = blockIdx.y, b = blockIdx.z;
    const float* Qg = g_q + ((size_t)(b * Hq + h) * Nq + qt * 128) * HDq;
    const float* Kg = g_k + (size_t)(b * Hq + h) * Nq * HDq;
    const float* Vg = g_v + (size_t)(b * Hq + h) * Nq * HDq;

    for (int l = tid; l < 128 * 64; l += 256) {
        int m = l >> 6, c = l & 63;
        Qs[c * SP + m] = Qg[m * HDq + c];
    }
    if (tid < 128) { mrow[tid] = -1e30f; lrow[tid] = 0.f; }

    ull op[4][4] = {};
    const ull sc2 = splat2(SCALE);

    for (int kt = 0; kt < Nq / 128; kt++) {
        __syncthreads();
        for (int l = tid; l < 128 * 64; l += 256) {
            int j = l >> 6, c = l & 63;
            Ks[c * SP + j] = Kg[(kt * 128 + j) * HDq + c];
            Vs[j * VP + c] = Vg[(kt * 128 + j) * HDq + c];
        }
        __syncthreads();
        {
            ull sp[8][4] = {};
            #pragma unroll 4
            for (int k = 0; k < HDq; k++) {
                float4 k0v = *(const float4*)&Ks[k * SP + tx * 8];
                float4 k1v = *(const float4*)&Ks[k * SP + tx * 8 + 4];
                ulonglong2 q0 = *(const ulonglong2*)&Qs[k * SP + ty * 8];
                ulonglong2 q1 = *(const ulonglong2*)&Qs[k * SP + ty * 8 + 4];
                ull qp[4] = {q0.x, q0.y, q1.x, q1.y};
                float kv[8] = {k0v.x, k0v.y, k0v.z, k0v.w, k1v.x, k1v.y, k1v.z, k1v.w};
                #pragma unroll
                for (int jj = 0; jj < 8; jj++) {
                    ull kk2 = splat2(kv[jj]);
                    #pragma unroll
                    for (int ip = 0; ip < 4; ip++)
                        sp[jj][ip] = fma2_(kk2, qp[ip], sp[jj][ip]);
                }
            }
            #pragma unroll
            for (int jj = 0; jj < 8; jj++)
                #pragma unroll
                for (int ip = 0; ip < 4; ip++)
                    *(ull*)&Ss[(tx * 8 + jj) * SP + ty * 8 + ip * 2] = mul2_(sp[jj][ip], sc2);
        }
        __syncthreads();
        {
            int row = tid >> 1, half = tid & 1;
            int jb = half * 64;
            float mx = -1e30f;
            #pragma unroll 8
            for (int j2 = 0; j2 < 64; j2++)
                mx = fmaxf(mx, Ss[(jb + j2) * SP + row]);
            mx = fmaxf(mx, __shfl_xor_sync(0xffffffffu, mx, 1));
            float mprev = mrow[row];
            float mnew = fmaxf(mprev, mx);
            float sum = 0.f;
            #pragma unroll 8
            for (int j2 = 0; j2 < 64; j2++) {
                float p = __expf(Ss[(jb + j2) * SP + row] - mnew);
                Ss[(jb + j2) * SP + row] = p;
                sum += p;
            }
            sum += __shfl_xor_sync(0xffffffffu, sum, 1);
            if (half == 0) {
                float al = __expf(mprev - mnew);
                mrow[row] = mnew;
                lrow[row] = lrow[row] * al + sum;
                arow[row] = al;
            }
        }
        __syncthreads();
        {
            #pragma unroll
            for (int mp = 0; mp < 4; mp++) {
                ull ap = *(const ull*)&arow[ty * 8 + mp * 2];
                #pragma unroll
                for (int nc = 0; nc < 4; nc++)
                    op[nc][mp] = mul2_(op[nc][mp], ap);
            }
            #pragma unroll 2
            for (int j = 0; j < 128; j++) {
                float4 vv = *(const float4*)&Vs[j * VP + tx * 4];
                ulonglong2 p0 = *(const ulonglong2*)&Ss[j * SP + ty * 8];
                ulonglong2 p1 = *(const ulonglong2*)&Ss[j * SP + ty * 8 + 4];
                ull pf[4] = {p0.x, p0.y, p1.x, p1.y};
                float va[4] = {vv.x, vv.y, vv.z, vv.w};
                #pragma unroll
                for (int nc = 0; nc < 4; nc++) {
                    ull v2 = splat2(va[nc]);
                    #pragma unroll
                    for (int mp = 0; mp < 4; mp++)
                        op[nc][mp] = fma2_(v2, pf[mp], op[nc][mp]);
                }
            }
        }
    }
    __syncthreads();

    float inv[8];
    #pragma unroll
    for (int r = 0; r < 8; r++) inv[r] = 1.f / lrow[ty * 8 + r];
    #pragma unroll
    for (int nc = 0; nc < 4; nc++) {
        int col = h * HDq + tx * 4 + nc;
        #pragma unroll
        for (int mp = 0; mp < 4; mp++) {
            float o0, o1;
            upk2(op[nc][mp], o0, o1);
            int m0 = ty * 8 + mp * 2;
            size_t row0 = (size_t)b * Nq + qt * 128 + m0;
            float a0 = o0 * inv[mp * 2], a1 = o1 * inv[mp * 2 + 1];
            bf16 hh, ll;
            split_bf16(a0, hh, ll);
            g_atth[row0 * Cq + col] = hh; g_attl[row0 * Cq + col] = ll;
            split_bf16(a1, hh, ll);
            g_atth[(row0 + 1) * Cq + col] = hh; g_attl[(row0 + 1) * Cq + col] = ll;
        }
    }
}

extern "C" void kernel_launch(void* const* d_in, const int* in_sizes, int n_in,
                              void* d_out, int out_size) {
    const float* x    = (const float*)d_in[0];
    const float* Wq   = (const float*)d_in[1];
    const float* Wk   = (const float*)d_in[2];
    const float* Wv   = (const float*)d_in[3];
    const float* Wp   = (const float*)d_in[4];
    const float* bp   = (const float*)d_in[5];
    const float* la_q = (const float*)d_in[6];
    const float* lb_q = (const float*)d_in[7];
    const float* la_k = (const float*)d_in[8];
    const float* lb_k = (const float*)d_in[9];
    const float* la_v = (const float*)d_in[10];
    const float* lb_v = (const float*)d_in[11];
    const float* bw   = (const float*)d_in[12];
    float* out = (float*)d_out;

    convert_x_kernel<<<(ROWS * Cq + 255) / 256, 256>>>(x);
    transpose_w_kernel<<<dim3(24, 24, 4), 256>>>(Wq, Wk, Wv, Wp);
    transpose_lb_kernel<<<(3 * Cq * 32 + 255) / 256, 256>>>(lb_q, lb_k, lb_v);
    lora_xa_kernel<<<ROWS / 16, 256>>>(x, la_q, la_k, la_v, bw);

    cudaFuncSetAttribute(gemm_qkv_kernel, cudaFuncAttributeMaxDynamicSharedMemorySize, GEMM_DSMEM);
    gemm_qkv_kernel<<<dim3(6, 64, 3), 256, GEMM_DSMEM>>>();

    size_t smem = (size_t)(64 * SP + 64 * SP + 128 * VP + 128 * SP + 3 * 128) * sizeof(float);
    cudaFuncSetAttribute(attn_kernel, cudaFuncAttributeMaxDynamicSharedMemorySize, (int)smem);
    attn_kernel<<<dim3(Nq / 128, Hq, Bq), 256, smem>>>();

    cudaFuncSetAttribute(gemm_out_kernel, cudaFuncAttributeMaxDynamicSharedMemorySize, GEMM_DSMEM);
    gemm_out_kernel<<<dim3(6, 64), 256, GEMM_DSMEM>>>(bp, out);
}